// round 16
// baseline (speedup 1.0000x reference)
#include <cuda_runtime.h>

#define NQ 9

// ---------- complex helpers ----------
struct C { float r, i; };
__device__ __forceinline__ C cmul(C a, C b)  { return {a.r * b.r - a.i * b.i, a.r * b.i + a.i * b.r}; }
__device__ __forceinline__ C cmulj(C a, C b) { return {a.r * b.r + a.i * b.i, a.i * b.r - a.r * b.i}; }  // a*conj(b)
__device__ __forceinline__ C cadd(C a, C b)  { return {a.r + b.r, a.i + b.i}; }
__device__ __forceinline__ C cscale(C a, float s) { return {a.r * s, a.i * s}; }

// A(z', z) scaling: (0,0)->a, (1,1)->-a, (0,1)->b, (1,0)->conj(b). r,c compile-time.
__device__ __forceinline__ C ascale(int r, int c, C X, float a, C b) {
    if (r == 0 && c == 0) return cscale(X, a);
    if (r == 1 && c == 1) return cscale(X, -a);
    if (r == 0 && c == 1) return cmul(X, b);
    return cmulj(X, b);
}

// delta-site (A = I): y[z] = sum_{b,b'} v(z^b) conj(v(z^b')) X[b][b']
__device__ __forceinline__ void collapse(const C vq[2], const C X[2][2], C y[2]) {
#pragma unroll
    for (int z = 0; z < 2; z++) {
        C R0 = cadd(cmulj(X[0][0], vq[z]), cmulj(X[0][1], vq[z ^ 1]));
        C R1 = cadd(cmulj(X[1][0], vq[z]), cmulj(X[1][1], vq[z ^ 1]));
        y[z] = cadd(cmul(vq[z], R0), cmul(vq[z ^ 1], R1));
    }
}

// S-site: X[z][z'] = A(z',z) * sum_b v(z^b) conj(v(z'^b)) y[b]
__device__ __forceinline__ void expand(const C vq[2], C X[2][2], const C y[2], float a, C b) {
    C t00 = cmul(vq[0], y[0]), t01 = cmul(vq[1], y[1]);
    C t10 = cmul(vq[1], y[0]), t11 = cmul(vq[0], y[1]);
#pragma unroll
    for (int zp = 0; zp < 2; zp++) {
        C e0 = cadd(cmulj(t00, vq[zp]), cmulj(t01, vq[zp ^ 1]));
        C e1 = cadd(cmulj(t10, vq[zp]), cmulj(t11, vq[zp ^ 1]));
        X[0][zp] = ascale(zp, 0, e0, a, b);
        X[1][zp] = ascale(zp, 1, e1, a, b);
    }
}

// Forward half: sites 0..4 (v[0..4] = v_0..v_4) for ONE wrap value.
// W8 enters only through the A0 record: W8=1 <=> (a0 -> -a0, b0 -> conj(b0)).
//   (verified per index: ascale(up^1,u^1,·,a,b) == ascale(up,u,·,-a,conj(b)))
__device__ __forceinline__ void fwd_chain(const C v[5][2], float a0, C b0,
                                          const float* Aa, const C* Ab, C y4[2]) {
    // site 0 (wrap): s[u][u'] = A0(u', u) v0(u) conj(v0(u'))
    C s[2][2];
#pragma unroll
    for (int u = 0; u < 2; u++)
#pragma unroll
        for (int up = 0; up < 2; up++)
            s[u][up] = ascale(up, u, cmulj(v[0][u], v[0][up]), a0, b0);
    // site 1: X[z][z'] = A1(z',z) sum_{u,u'} v1(z^u) conj(v1(z'^u')) s[u][u']
    C X[2][2];
    {
        C W_[2][2];
#pragma unroll
        for (int z = 0; z < 2; z++)
#pragma unroll
            for (int up = 0; up < 2; up++)
                W_[z][up] = cadd(cmul(v[1][z], s[0][up]), cmul(v[1][z ^ 1], s[1][up]));
#pragma unroll
        for (int z = 0; z < 2; z++)
#pragma unroll
            for (int zp = 0; zp < 2; zp++)
                X[z][zp] = ascale(zp, z,
                                  cadd(cmulj(W_[z][0], v[1][zp]), cmulj(W_[z][1], v[1][zp ^ 1])),
                                  Aa[1], Ab[1]);
    }
    C y2[2];
    collapse(v[2], X, y2);
    expand(v[3], X, y2, Aa[2], Ab[2]);   // A3
    collapse(v[4], X, y4);
}

// Backward half (adjoint): sites 8..5 (v[0]=v5, v[1]=v6, v[2]=v7, v[3]=v8) for ONE
// wrap value. W8 enters only through the closure: W8=1 <=> swap v8's two components
// (caller pre-swaps). Produces G s.t. E_w = sum_b G[b] * y4[b].
__device__ __forceinline__ void bwd_chain(const C v[4][2], const float* Aa, const C* Ab, C G[2]) {
    C T[2][2];
#pragma unroll
    for (int z = 0; z < 2; z++)
#pragma unroll
        for (int zp = 0; zp < 2; zp++)
            T[z][zp] = cmulj(v[3][z], v[3][zp]);
    // back through site 7 (A7 = Aa[4])
#pragma unroll
    for (int z = 0; z < 2; z++)
#pragma unroll
        for (int zp = 0; zp < 2; zp++)
            T[z][zp] = ascale(zp, z, T[z][zp], Aa[4], Ab[4]);
    C G7[2];
#pragma unroll
    for (int bb = 0; bb < 2; bb++) {
        C in0 = cadd(cmulj(T[0][0], v[2][bb]), cmulj(T[0][1], v[2][bb ^ 1]));
        C in1 = cadd(cmulj(T[1][0], v[2][bb]), cmulj(T[1][1], v[2][bb ^ 1]));
        G7[bb] = cadd(cmul(v[2][bb], in0), cmul(v[2][bb ^ 1], in1));
    }
    // back through site 6 (delta)
    C T6[2][2];
#pragma unroll
    for (int bb = 0; bb < 2; bb++)
#pragma unroll
        for (int bp = 0; bp < 2; bp++)
            T6[bb][bp] = cadd(cmul(G7[0], cmulj(v[1][bb], v[1][bp])),
                              cmul(G7[1], cmulj(v[1][bb ^ 1], v[1][bp ^ 1])));
    // back through site 5 (A5 = Aa[3])
#pragma unroll
    for (int z = 0; z < 2; z++)
#pragma unroll
        for (int zp = 0; zp < 2; zp++)
            T6[z][zp] = ascale(zp, z, T6[z][zp], Aa[3], Ab[3]);
#pragma unroll
    for (int bb = 0; bb < 2; bb++) {
        C in0 = cadd(cmulj(T6[0][0], v[0][bb]), cmulj(T6[0][1], v[0][bb ^ 1]));
        C in1 = cadd(cmulj(T6[1][0], v[0][bb]), cmulj(T6[1][1], v[0][bb ^ 1]));
        G[bb] = cadd(cmul(v[0][bb], in0), cmul(v[0][bb ^ 1], in1));
    }
}

// 4 threads per patch: (role = fwd/bwd) x (w8 = 0/1), all warp-uniform.
// Block = 256 threads = 8 warps = 2 groups of 32 patches; warp&3 selects
// (w8, role). Combine through smem: bwd publishes G, fwd(w8) computes E_w,
// fwd(w8=1) publishes E_1, fwd(w8=0) stores E_0 + E_1.
__global__ void __launch_bounds__(256) qk_main(const float* __restrict__ x,
                                               const float* __restrict__ wts,
                                               float* __restrict__ out, int n_patch) {
    __shared__ float4 sv[NQ * 2];
    __shared__ float  sAa[5];
    __shared__ float2 sAb[5];
    __shared__ float  sG[2][4][64];   // [w8][component][slot] — conflict-free
    __shared__ float  sE1[64];        // E_1 partial per slot

    const int t = threadIdx.x;
    if (t < NQ) {
        float phi = wts[t * 3 + 0], theta = wts[t * 3 + 1], omega = wts[t * 3 + 2];
        float st, ct; __sincosf(0.5f * theta, &st, &ct);
        float sp, cp; __sincosf(0.5f * (phi + omega), &sp, &cp);
        float sm, cm; __sincosf(0.5f * (phi - omega), &sm, &cm);
        sv[t * 2]     = make_float4(cp * ct, -sp * ct, cm * st, -sm * st);
        // m = -i*u_col1: u01=(-cm*st,-sm*st) -> (-sm*st, cm*st); u11=(cp*ct,sp*ct) -> (sp*ct,-cp*ct)
        sv[t * 2 + 1] = make_float4(-sm * st, cm * st, sp * ct, -cp * ct);
    }
    if (t < 5) {
        const int ql[5] = {0, 1, 3, 5, 7};
        const int j = NQ + ql[t];
        float phi = wts[j * 3 + 0], theta = wts[j * 3 + 1], omega = wts[j * 3 + 2];
        float st, ct; __sincosf(0.5f * theta, &st, &ct);
        float sp, cp; __sincosf(0.5f * (phi + omega), &sp, &cp);
        float sm, cm; __sincosf(0.5f * (phi - omega), &sm, &cm);
        float u00r = cp * ct, u00i = -sp * ct;
        float u01r = -cm * st, u01i = -sm * st;
        float u10r = cm * st,  u10i = -sm * st;
        float u11r = cp * ct,  u11i = sp * ct;
        sAa[t] = (u00r * u00r + u00i * u00i) - (u10r * u10r + u10i * u10i);
        sAb[t] = make_float2((u00r * u01r + u00i * u01i) - (u10r * u11r + u10i * u11i),
                             (u00r * u01i - u00i * u01r) - (u10r * u11i - u10i * u11r));
    }
    __syncthreads();

    const int lane = t & 31;
    const int warp = t >> 5;          // 0..7
    const int group = warp >> 2;      // 0..1
    const int w8 = (warp >> 1) & 1;   // wrap value
    const int role = warp & 1;        // 0 = forward, 1 = backward
    const int slot = group * 32 + lane;
    int p = blockIdx.x * 64 + slot;
    const bool valid = p < n_patch;
    if (!valid) p = n_patch - 1;      // clamp; barriers stay uniform
    const int bb_ = p >> 12, h = (p >> 6) & 63, w = p & 63;

    float Aa[5]; C Ab[5];
#pragma unroll
    for (int i = 0; i < 5; i++) { Aa[i] = sAa[i]; Ab[i] = {sAb[i].x, sAb[i].y}; }

    C y[2];  // forward output (role 0)
    if (role == 0) {
        C v[5][2];
#pragma unroll
        for (int k = 0; k < 5; k++) {
            const int q = k;
            const int hh = h - 1 + q / 3, ww = w - 1 + q % 3;
            float a = 0.0f;
            if (hh >= 0 && hh < 64 && ww >= 0 && ww < 64)
                a = __ldg(&x[(bb_ << 12) + (hh << 6) + ww]);
            float s_, c_; __sincosf(0.5f * a, &s_, &c_);
            const float4 A = sv[2 * q], B = sv[2 * q + 1];
            v[k][0] = {A.x * c_ + B.x * s_, A.y * c_ + B.y * s_};
            v[k][1] = {A.z * c_ + B.z * s_, A.w * c_ + B.w * s_};
        }
        const float a0 = w8 ? -Aa[0] : Aa[0];
        const C b0 = {Ab[0].r, w8 ? -Ab[0].i : Ab[0].i};  // conj for w8=1
        fwd_chain(v, a0, b0, Aa, Ab, y);
    } else {
        C v[4][2];
#pragma unroll
        for (int k = 0; k < 4; k++) {
            const int q = 5 + k;
            const int hh = h - 1 + q / 3, ww = w - 1 + q % 3;
            float a = 0.0f;
            if (hh >= 0 && hh < 64 && ww >= 0 && ww < 64)
                a = __ldg(&x[(bb_ << 12) + (hh << 6) + ww]);
            float s_, c_; __sincosf(0.5f * a, &s_, &c_);
            const float4 A = sv[2 * q], B = sv[2 * q + 1];
            v[k][0] = {A.x * c_ + B.x * s_, A.y * c_ + B.y * s_};
            v[k][1] = {A.z * c_ + B.z * s_, A.w * c_ + B.w * s_};
        }
        if (w8) { C tmp = v[3][0]; v[3][0] = v[3][1]; v[3][1] = tmp; }  // closure swap
        C G[2];
        bwd_chain(v, Aa, Ab, G);
        sG[w8][0][slot] = G[0].r; sG[w8][1][slot] = G[0].i;
        sG[w8][2][slot] = G[1].r; sG[w8][3][slot] = G[1].i;
    }

    __syncthreads();

    float Ew = 0.0f;
    if (role == 0) {
        // E_w = Re( sum_b y[b] * G_w[b] )
        Ew = y[0].r * sG[w8][0][slot] - y[0].i * sG[w8][1][slot]
           + y[1].r * sG[w8][2][slot] - y[1].i * sG[w8][3][slot];
        if (w8 == 1) sE1[slot] = Ew;
    }
    __syncthreads();

    if (role == 0 && w8 == 0 && valid)
        out[p] = Ew + sE1[slot];
}

extern "C" void kernel_launch(void* const* d_in, const int* in_sizes, int n_in,
                              void* d_out, int out_size) {
    const float* x;
    const float* wts;
    if (n_in >= 2 && in_sizes[0] == 2 * NQ * 3) {
        wts = (const float*)d_in[0];
        x = (const float*)d_in[1];
    } else {
        x = (const float*)d_in[0];
        wts = (const float*)d_in[1];
    }

    const int n_patch = out_size;                 // 32768
    const int patches_per_block = 64;             // 2 groups x 32 patches, 4 thr/patch
    const int blocks = (n_patch + patches_per_block - 1) / patches_per_block;  // 512
    qk_main<<<blocks, 256>>>(x, wts, (float*)d_out, n_patch);
}

// round 17
// speedup vs baseline: 1.2917x; 1.2917x over previous
#include <cuda_runtime.h>

#define NQ 9

// ---------- complex helpers ----------
struct C { float r, i; };
__device__ __forceinline__ C cmul(C a, C b)  { return {a.r * b.r - a.i * b.i, a.r * b.i + a.i * b.r}; }
__device__ __forceinline__ C cmulj(C a, C b) { return {a.r * b.r + a.i * b.i, a.i * b.r - a.r * b.i}; }  // a*conj(b)
__device__ __forceinline__ C cadd(C a, C b)  { return {a.r + b.r, a.i + b.i}; }
__device__ __forceinline__ C cscale(C a, float s) { return {a.r * s, a.i * s}; }

// A(z', z) scaling: (0,0)->a, (1,1)->-a, (0,1)->b, (1,0)->conj(b). r,c compile-time.
__device__ __forceinline__ C ascale(int r, int c, C X, float a, C b) {
    if (r == 0 && c == 0) return cscale(X, a);
    if (r == 1 && c == 1) return cscale(X, -a);
    if (r == 0 && c == 1) return cmul(X, b);
    return cmulj(X, b);
}

// delta-site (A = I): y[z] = sum_{b,b'} v(z^b) conj(v(z^b')) X[b][b']
__device__ __forceinline__ void collapse(const C vq[2], const C X[2][2], C y[2]) {
#pragma unroll
    for (int z = 0; z < 2; z++) {
        C R0 = cadd(cmulj(X[0][0], vq[z]), cmulj(X[0][1], vq[z ^ 1]));
        C R1 = cadd(cmulj(X[1][0], vq[z]), cmulj(X[1][1], vq[z ^ 1]));
        y[z] = cadd(cmul(vq[z], R0), cmul(vq[z ^ 1], R1));
    }
}

// S-site: X[z][z'] = A(z',z) * sum_b v(z^b) conj(v(z'^b)) y[b]
__device__ __forceinline__ void expand(const C vq[2], C X[2][2], const C y[2], float a, C b) {
    C t00 = cmul(vq[0], y[0]), t01 = cmul(vq[1], y[1]);
    C t10 = cmul(vq[1], y[0]), t11 = cmul(vq[0], y[1]);
#pragma unroll
    for (int zp = 0; zp < 2; zp++) {
        C e0 = cadd(cmulj(t00, vq[zp]), cmulj(t01, vq[zp ^ 1]));
        C e1 = cadd(cmulj(t10, vq[zp]), cmulj(t11, vq[zp ^ 1]));
        X[0][zp] = ascale(zp, 0, e0, a, b);
        X[1][zp] = ascale(zp, 1, e1, a, b);
    }
}

// Forward half: sites 0..4 (v[0..4] = v_0..v_4). Output y4 per wrap value W8.
template <int W8>
__device__ __forceinline__ void fwd_chain(const C v[5][2], const float* Aa, const C* Ab, C y4[2]) {
    // site 0 (wrap): s[u][u'] = A0(u'^W8, u^W8) v0(u) conj(v0(u'))
    C s[2][2];
#pragma unroll
    for (int u = 0; u < 2; u++)
#pragma unroll
        for (int up = 0; up < 2; up++)
            s[u][up] = ascale(up ^ W8, u ^ W8, cmulj(v[0][u], v[0][up]), Aa[0], Ab[0]);
    // site 1: X[z][z'] = A1(z',z) sum_{u,u'} v1(z^u) conj(v1(z'^u')) s[u][u']
    C X[2][2];
    {
        C W_[2][2];
#pragma unroll
        for (int z = 0; z < 2; z++)
#pragma unroll
            for (int up = 0; up < 2; up++)
                W_[z][up] = cadd(cmul(v[1][z], s[0][up]), cmul(v[1][z ^ 1], s[1][up]));
#pragma unroll
        for (int z = 0; z < 2; z++)
#pragma unroll
            for (int zp = 0; zp < 2; zp++)
                X[z][zp] = ascale(zp, z,
                                  cadd(cmulj(W_[z][0], v[1][zp]), cmulj(W_[z][1], v[1][zp ^ 1])),
                                  Aa[1], Ab[1]);
    }
    C y2[2];
    collapse(v[2], X, y2);
    expand(v[3], X, y2, Aa[2], Ab[2]);   // A3
    collapse(v[4], X, y4);
}

// Backward half (adjoint): sites 8..5 (v[0]=v5, v[1]=v6, v[2]=v7, v[3]=v8).
// Produces G s.t. E_w = sum_b G[b] * y4[b].
template <int W8>
__device__ __forceinline__ void bwd_chain(const C v[4][2], const float* Aa, const C* Ab, C G[2]) {
    C T[2][2];
#pragma unroll
    for (int z = 0; z < 2; z++)
#pragma unroll
        for (int zp = 0; zp < 2; zp++)
            T[z][zp] = cmulj(v[3][W8 ^ z], v[3][W8 ^ zp]);
    // back through site 7 (A7 = Aa[4])
#pragma unroll
    for (int z = 0; z < 2; z++)
#pragma unroll
        for (int zp = 0; zp < 2; zp++)
            T[z][zp] = ascale(zp, z, T[z][zp], Aa[4], Ab[4]);
    C G7[2];
#pragma unroll
    for (int bb = 0; bb < 2; bb++) {
        C in0 = cadd(cmulj(T[0][0], v[2][bb]), cmulj(T[0][1], v[2][bb ^ 1]));
        C in1 = cadd(cmulj(T[1][0], v[2][bb]), cmulj(T[1][1], v[2][bb ^ 1]));
        G7[bb] = cadd(cmul(v[2][bb], in0), cmul(v[2][bb ^ 1], in1));
    }
    // back through site 6 (delta)
    C T6[2][2];
#pragma unroll
    for (int bb = 0; bb < 2; bb++)
#pragma unroll
        for (int bp = 0; bp < 2; bp++)
            T6[bb][bp] = cadd(cmul(G7[0], cmulj(v[1][bb], v[1][bp])),
                              cmul(G7[1], cmulj(v[1][bb ^ 1], v[1][bp ^ 1])));
    // back through site 5 (A5 = Aa[3])
#pragma unroll
    for (int z = 0; z < 2; z++)
#pragma unroll
        for (int zp = 0; zp < 2; zp++)
            T6[z][zp] = ascale(zp, z, T6[z][zp], Aa[3], Ab[3]);
#pragma unroll
    for (int bb = 0; bb < 2; bb++) {
        C in0 = cadd(cmulj(T6[0][0], v[0][bb]), cmulj(T6[0][1], v[0][bb ^ 1]));
        C in1 = cadd(cmulj(T6[1][0], v[0][bb]), cmulj(T6[1][1], v[0][bb ^ 1]));
        G[bb] = cadd(cmul(v[0][bb], in0), cmul(v[0][bb ^ 1], in1));
    }
}

// R14 structure (best): 2 threads/patch (fwd/bwd role per warp), 128-thread blocks.
// R16 change: x-angle loads + sincos hoisted ABOVE the table __syncthreads so the
// DRAM latency of x overlaps the table-build (wts load + sincos) critical path.
__global__ void __launch_bounds__(128) qk_main(const float* __restrict__ x,
                                               const float* __restrict__ wts,
                                               float* __restrict__ out, int n_patch) {
    __shared__ float4 sv[NQ * 2];
    __shared__ float  sAa[5];
    __shared__ float2 sAb[5];
    __shared__ float  sG[8][64];   // G per patch-slot, component-major (conflict-free)

    const int t = threadIdx.x;
    const int lane = t & 31;
    const int warp = t >> 5;          // 0..3
    const int pair = warp >> 1;       // 0..1
    const int role = warp & 1;        // 0 = forward (q 0..4), 1 = backward (q 5..8)
    const int slot = pair * 32 + lane;
    int p = blockIdx.x * 64 + slot;
    const bool valid = p < n_patch;
    if (!valid) p = n_patch - 1;      // clamp; barriers stay uniform
    const int bb_ = p >> 12, h = (p >> 6) & 63, w = p & 63;

    // ---- table build (threads 0..8 / 0..4) — issued first so wts LDG starts early ----
    if (t < NQ) {
        float phi = wts[t * 3 + 0], theta = wts[t * 3 + 1], omega = wts[t * 3 + 2];
        float st, ct; __sincosf(0.5f * theta, &st, &ct);
        float sp, cp; __sincosf(0.5f * (phi + omega), &sp, &cp);
        float sm, cm; __sincosf(0.5f * (phi - omega), &sm, &cm);
        sv[t * 2]     = make_float4(cp * ct, -sp * ct, cm * st, -sm * st);
        // m = -i*u_col1: u01=(-cm*st,-sm*st) -> (-sm*st, cm*st); u11=(cp*ct,sp*ct) -> (sp*ct,-cp*ct)
        sv[t * 2 + 1] = make_float4(-sm * st, cm * st, sp * ct, -cp * ct);
    }
    if (t < 5) {
        const int ql[5] = {0, 1, 3, 5, 7};
        const int j = NQ + ql[t];
        float phi = wts[j * 3 + 0], theta = wts[j * 3 + 1], omega = wts[j * 3 + 2];
        float st, ct; __sincosf(0.5f * theta, &st, &ct);
        float sp, cp; __sincosf(0.5f * (phi + omega), &sp, &cp);
        float sm, cm; __sincosf(0.5f * (phi - omega), &sm, &cm);
        float u00r = cp * ct, u00i = -sp * ct;
        float u01r = -cm * st, u01i = -sm * st;
        float u10r = cm * st,  u10i = -sm * st;
        float u11r = cp * ct,  u11i = sp * ct;
        sAa[t] = (u00r * u00r + u00i * u00i) - (u10r * u10r + u10i * u10i);
        sAb[t] = make_float2((u00r * u01r + u00i * u01i) - (u10r * u11r + u10i * u11i),
                             (u00r * u01i - u00i * u01r) - (u10r * u11i - u10i * u11r));
    }

    // ---- angle loads + sincos for this thread's qubits — BEFORE the barrier ----
    const int nq_mine = (role == 0) ? 5 : 4;
    const int qbase = (role == 0) ? 0 : 5;
    float cs[5], sn[5];
#pragma unroll
    for (int k = 0; k < 5; k++) {
        if (k >= nq_mine) break;
        const int q = qbase + k;
        const int hh = h - 1 + q / 3, ww = w - 1 + q % 3;
        float a = 0.0f;
        if (hh >= 0 && hh < 64 && ww >= 0 && ww < 64)
            a = __ldg(&x[(bb_ << 12) + (hh << 6) + ww]);
        __sincosf(0.5f * a, &sn[k], &cs[k]);
    }

    __syncthreads();

    float Aa[5]; C Ab[5];
#pragma unroll
    for (int i = 0; i < 5; i++) { Aa[i] = sAa[i]; Ab[i] = {sAb[i].x, sAb[i].y}; }

    C y0[2], y1[2];  // forward outputs (role 0 only)
    if (role == 0) {
        C v[5][2];
#pragma unroll
        for (int k = 0; k < 5; k++) {
            const float4 A = sv[2 * k], B = sv[2 * k + 1];
            v[k][0] = {A.x * cs[k] + B.x * sn[k], A.y * cs[k] + B.y * sn[k]};
            v[k][1] = {A.z * cs[k] + B.z * sn[k], A.w * cs[k] + B.w * sn[k]};
        }
        fwd_chain<0>(v, Aa, Ab, y0);
        fwd_chain<1>(v, Aa, Ab, y1);
    } else {
        C v[4][2];
#pragma unroll
        for (int k = 0; k < 4; k++) {
            const int q = 5 + k;
            const float4 A = sv[2 * q], B = sv[2 * q + 1];
            v[k][0] = {A.x * cs[k] + B.x * sn[k], A.y * cs[k] + B.y * sn[k]};
            v[k][1] = {A.z * cs[k] + B.z * sn[k], A.w * cs[k] + B.w * sn[k]};
        }
        C G0[2], G1[2];
        bwd_chain<0>(v, Aa, Ab, G0);
        bwd_chain<1>(v, Aa, Ab, G1);
        sG[0][slot] = G0[0].r; sG[1][slot] = G0[0].i;
        sG[2][slot] = G0[1].r; sG[3][slot] = G0[1].i;
        sG[4][slot] = G1[0].r; sG[5][slot] = G1[0].i;
        sG[6][slot] = G1[1].r; sG[7][slot] = G1[1].i;
    }

    __syncthreads();

    if (role == 0) {
        // E = Re( sum_w sum_b y_w[b] * G_w[b] )
        float E = y0[0].r * sG[0][slot] - y0[0].i * sG[1][slot]
                + y0[1].r * sG[2][slot] - y0[1].i * sG[3][slot]
                + y1[0].r * sG[4][slot] - y1[0].i * sG[5][slot]
                + y1[1].r * sG[6][slot] - y1[1].i * sG[7][slot];
        if (valid) out[p] = E;
    }
}

extern "C" void kernel_launch(void* const* d_in, const int* in_sizes, int n_in,
                              void* d_out, int out_size) {
    const float* x;
    const float* wts;
    if (n_in >= 2 && in_sizes[0] == 2 * NQ * 3) {
        wts = (const float*)d_in[0];
        x = (const float*)d_in[1];
    } else {
        x = (const float*)d_in[0];
        wts = (const float*)d_in[1];
    }

    const int n_patch = out_size;                 // 32768
    const int patches_per_block = 64;             // 2 warp-pairs x 32 patches
    const int blocks = (n_patch + patches_per_block - 1) / patches_per_block;  // 512
    qk_main<<<blocks, 128>>>(x, wts, (float*)d_out, n_patch);
}